// round 3
// baseline (speedup 1.0000x reference)
#include <cuda_runtime.h>
#include <cstdint>
#include <cstddef>

// Problem constants
#define NB 8
#define NH 12
#define SQ 1024          // all of SEN_LEN / SP_LEN / P_LEN
#define DH 64
#define EMB 768
#define BHC (NB*NH)      // 96

// ---------------- scratch (static device globals; no allocation) ----------------
__device__ float g_q  [NB*NH*SQ*DH];   // [b,h,s,d]
__device__ float g_ksp[NB*NH*SQ*DH];
__device__ float g_kp [NB*NH*SQ*DH];
__device__ float g_vsp[NB*NH*SQ*DH];
__device__ float g_A1 [100663296];     // [bh][k][s]  = softmax_s(ksp_k . q_s)
__device__ float g_A2 [100663296];     // [bh][p][s]  = softmax_s(kp_p . q_s)
__device__ float g_SP [100663296];     // [bh][p][k]  sp2p
__device__ float g_ctx[NB*SQ*EMB];     // [b,p, h*64+d]

// =================================================================================
// NT GEMM, 128x128 tile, BK=8, 256 threads, 8x8 micro-tile.
// C[m,n] = sum_k A[m,k]*B[n,k]   (A: [M,K] rm, B: [N,K] rm)
// EPI 0: plain store to C (ldc)
// EPI 1: (acc + bias[n]) * alpha, store to head layout [b,h,s,d] (m=b*1024+s, n=h*64+d)
// EPI 2: (acc + bias[n]) * alpha, plain store to C (ldc)
// =================================================================================
template<int EPI>
__global__ void __launch_bounds__(256)
gemm_nt128(const float* __restrict__ Ab, const float* __restrict__ Bb,
           float* __restrict__ Cb, const float* __restrict__ bias,
           int K, int ldc, float alpha,
           size_t sA, size_t sB, size_t sC)
{
    const int m0 = blockIdx.y * 128;
    const int n0 = blockIdx.x * 128;
    const float* A  = Ab + (size_t)blockIdx.z * sA + (size_t)m0 * K;
    const float* Bp = Bb + (size_t)blockIdx.z * sB + (size_t)n0 * K;
    float* C = Cb + (size_t)blockIdx.z * sC;

    __shared__ float As[8][128];
    __shared__ float Bs[8][128];

    const int tid = threadIdx.x;
    const int lr = tid >> 1;            // 0..127
    const int lc = (tid & 1) * 4;       // 0 or 4
    const int tx = tid & 15;
    const int ty = tid >> 4;

    float acc[8][8];
    #pragma unroll
    for (int i = 0; i < 8; i++)
        #pragma unroll
        for (int j = 0; j < 8; j++) acc[i][j] = 0.f;

    for (int k0 = 0; k0 < K; k0 += 8) {
        float4 av = *(const float4*)(A  + (size_t)lr * K + k0 + lc);
        float4 bv = *(const float4*)(Bp + (size_t)lr * K + k0 + lc);
        __syncthreads();
        As[lc+0][lr] = av.x; As[lc+1][lr] = av.y; As[lc+2][lr] = av.z; As[lc+3][lr] = av.w;
        Bs[lc+0][lr] = bv.x; Bs[lc+1][lr] = bv.y; Bs[lc+2][lr] = bv.z; Bs[lc+3][lr] = bv.w;
        __syncthreads();

        #pragma unroll
        for (int kk = 0; kk < 8; kk++) {
            float a[8], b[8];
            *(float4*)&a[0] = *(const float4*)&As[kk][ty*4];
            *(float4*)&a[4] = *(const float4*)&As[kk][64 + ty*4];
            *(float4*)&b[0] = *(const float4*)&Bs[kk][tx*4];
            *(float4*)&b[4] = *(const float4*)&Bs[kk][64 + tx*4];
            #pragma unroll
            for (int i = 0; i < 8; i++)
                #pragma unroll
                for (int j = 0; j < 8; j++)
                    acc[i][j] += a[i] * b[j];
        }
    }

    #pragma unroll
    for (int i = 0; i < 8; i++) {
        int m = m0 + ((i < 4) ? (ty*4 + i) : (64 + ty*4 + i - 4));
        #pragma unroll
        for (int j = 0; j < 8; j++) {
            int n = n0 + ((j < 4) ? (tx*4 + j) : (64 + tx*4 + j - 4));
            if (EPI == 0) {
                C[(size_t)m * ldc + n] = acc[i][j];
            } else {
                float v = (acc[i][j] + bias[n]) * alpha;
                if (EPI == 1) {
                    int bb = m >> 10, s = m & 1023;
                    int h  = n >> 6,  d = n & 63;
                    C[((((size_t)bb * NH + h) * SQ) + s) * DH + d] = v;
                } else {
                    C[(size_t)m * ldc + n] = v;
                }
            }
        }
    }
}

// =================================================================================
// NN GEMM for attention-out: per (b,h): ctx = SP[1024,1024] @ V[1024,64]
// 64x64 tile, BK=16, 256 threads, 4x4 micro-tile. Stores into ctx [b,p, h*64+d].
// =================================================================================
__global__ void __launch_bounds__(256)
gemm_nn_ctx(const float* __restrict__ Sp, const float* __restrict__ V, float* __restrict__ ctx)
{
    const int bh = blockIdx.z;
    const int b = bh / NH, h = bh % NH;
    const int m0 = blockIdx.y * 64;
    const float* A  = Sp + (size_t)bh * SQ * SQ + (size_t)m0 * SQ;
    const float* Bv = V  + (size_t)bh * SQ * DH;

    __shared__ float As[16][64];
    __shared__ float Bs[16][64];

    const int tid = threadIdx.x;
    const int alr = tid >> 2, alc = (tid & 3) * 4;     // A: 64 rows x 16 k
    const int bkr = tid >> 4, bnc = (tid & 15) * 4;    // B: 16 k x 64 n
    const int tx = tid & 15, ty = tid >> 4;

    float acc[4][4];
    #pragma unroll
    for (int i = 0; i < 4; i++)
        #pragma unroll
        for (int j = 0; j < 4; j++) acc[i][j] = 0.f;

    for (int k0 = 0; k0 < SQ; k0 += 16) {
        float4 av = *(const float4*)(A  + (size_t)alr * SQ + k0 + alc);
        float4 bv = *(const float4*)(Bv + (size_t)(k0 + bkr) * DH + bnc);
        __syncthreads();
        As[alc+0][alr] = av.x; As[alc+1][alr] = av.y; As[alc+2][alr] = av.z; As[alc+3][alr] = av.w;
        *(float4*)&Bs[bkr][bnc] = bv;
        __syncthreads();

        #pragma unroll
        for (int kk = 0; kk < 16; kk++) {
            float4 a = *(const float4*)&As[kk][ty*4];
            float4 bq4 = *(const float4*)&Bs[kk][tx*4];
            acc[0][0] += a.x*bq4.x; acc[0][1] += a.x*bq4.y; acc[0][2] += a.x*bq4.z; acc[0][3] += a.x*bq4.w;
            acc[1][0] += a.y*bq4.x; acc[1][1] += a.y*bq4.y; acc[1][2] += a.y*bq4.z; acc[1][3] += a.y*bq4.w;
            acc[2][0] += a.z*bq4.x; acc[2][1] += a.z*bq4.y; acc[2][2] += a.z*bq4.z; acc[2][3] += a.z*bq4.w;
            acc[3][0] += a.w*bq4.x; acc[3][1] += a.w*bq4.y; acc[3][2] += a.w*bq4.z; acc[3][3] += a.w*bq4.w;
        }
    }

    #pragma unroll
    for (int i = 0; i < 4; i++) {
        int pIdx = m0 + ty * 4 + i;
        float* dst = ctx + ((size_t)(b * SQ + pIdx)) * EMB + h * DH + tx * 4;
        dst[0] = acc[i][0]; dst[1] = acc[i][1]; dst[2] = acc[i][2]; dst[3] = acc[i][3];
    }
}

// =================================================================================
// Row softmax over rows of length 1024 (contiguous). One 256-thread block per row.
// =================================================================================
__global__ void __launch_bounds__(256)
softmax_rows(float* __restrict__ data)
{
    float* row = data + (size_t)blockIdx.x * 1024;
    const int t = threadIdx.x;
    __shared__ float red[8];

    float4 v = ((float4*)row)[t];
    float m = fmaxf(fmaxf(v.x, v.y), fmaxf(v.z, v.w));
    #pragma unroll
    for (int o = 16; o; o >>= 1) m = fmaxf(m, __shfl_xor_sync(0xffffffffu, m, o));
    if ((t & 31) == 0) red[t >> 5] = m;
    __syncthreads();
    m = red[0];
    #pragma unroll
    for (int i = 1; i < 8; i++) m = fmaxf(m, red[i]);

    v.x = __expf(v.x - m); v.y = __expf(v.y - m);
    v.z = __expf(v.z - m); v.w = __expf(v.w - m);
    float s = v.x + v.y + v.z + v.w;
    #pragma unroll
    for (int o = 16; o; o >>= 1) s += __shfl_xor_sync(0xffffffffu, s, o);
    __syncthreads();               // protect red[] reuse
    if ((t & 31) == 0) red[t >> 5] = s;
    __syncthreads();
    s = red[0];
    #pragma unroll
    for (int i = 1; i < 8; i++) s += red[i];

    float inv = 1.0f / s;
    v.x *= inv; v.y *= inv; v.z *= inv; v.w *= inv;
    ((float4*)row)[t] = v;
}

// =================================================================================
extern "C" void kernel_launch(void* const* d_in, const int* in_sizes, int n_in,
                              void* d_out, int out_size)
{
    const float* l    = (const float*)d_in[0];
    const float* sp   = (const float*)d_in[1];
    const float* pp   = (const float*)d_in[2];
    const float* Wq   = (const float*)d_in[3];
    const float* bq   = (const float*)d_in[4];
    const float* Wksp = (const float*)d_in[5];
    const float* bksp = (const float*)d_in[6];
    const float* Wkp  = (const float*)d_in[7];
    const float* bkp  = (const float*)d_in[8];
    const float* Wvsp = (const float*)d_in[9];
    const float* bvsp = (const float*)d_in[10];
    const float* Wo   = (const float*)d_in[13];
    const float* bo   = (const float*)d_in[14];
    float* out = (float*)d_out;

    // Materialize module globals (forces eager load on the correctness call,
    // before graph capture begins). These are host-side, non-captured API calls.
    float *q, *ksp, *kp, *vsp, *A1, *A2, *SP, *ctx;
    cudaGetSymbolAddress((void**)&q,   g_q);
    cudaGetSymbolAddress((void**)&ksp, g_ksp);
    cudaGetSymbolAddress((void**)&kp,  g_kp);
    cudaGetSymbolAddress((void**)&vsp, g_vsp);
    cudaGetSymbolAddress((void**)&A1,  g_A1);
    cudaGetSymbolAddress((void**)&A2,  g_A2);
    cudaGetSymbolAddress((void**)&SP,  g_SP);
    cudaGetSymbolAddress((void**)&ctx, g_ctx);

    const float scale = 0.125f;  // 64^-0.5
    const size_t sHead = (size_t)SQ * DH;         // 65536 per (b,h)
    const size_t sMat  = (size_t)SQ * SQ;         // 1048576 per (b,h)

    dim3 gProj(EMB / 128, (NB * SQ) / 128, 1);    // (6, 64)

    // Projections -> head layout [b,h,s,d], scaled by 0.125 (bias inside)
    gemm_nt128<1><<<gProj, 256>>>(l,  Wq,   q,   bq,   EMB, 0, scale, 0, 0, 0);
    gemm_nt128<1><<<gProj, 256>>>(sp, Wksp, ksp, bksp, EMB, 0, scale, 0, 0, 0);
    gemm_nt128<1><<<gProj, 256>>>(pp, Wkp,  kp,  bkp,  EMB, 0, scale, 0, 0, 0);
    gemm_nt128<1><<<gProj, 256>>>(sp, Wvsp, vsp, bvsp, EMB, 0, scale, 0, 0, 0);

    // Transposed logits: A1[k,s] = ksp_k . q_s ; A2[p,s] = kp_p . q_s
    dim3 gLog(SQ / 128, SQ / 128, BHC);           // (8, 8, 96)
    gemm_nt128<0><<<gLog, 256>>>(ksp, q, A1, nullptr, DH, SQ, 1.f, sHead, sHead, sMat);
    gemm_nt128<0><<<gLog, 256>>>(kp,  q, A2, nullptr, DH, SQ, 1.f, sHead, sHead, sMat);

    // softmax over s (now row-wise)
    softmax_rows<<<BHC * SQ, 256>>>(A1);
    softmax_rows<<<BHC * SQ, 256>>>(A2);

    // sp2p[p,k] = sum_s A2[p,s] * A1[k,s]  (the 1024^3 x 96 GEMM)
    gemm_nt128<0><<<gLog, 256>>>(A2, A1, SP, nullptr, SQ, SQ, 1.f, sMat, sMat, sMat);

    // softmax over k (row-wise)
    softmax_rows<<<BHC * SQ, 256>>>(SP);

    // ctx[b,p,h*64+d] = sum_k SP[p,k] * vsp[k,d]
    dim3 gOut(1, SQ / 64, BHC);                   // (1, 16, 96)
    gemm_nn_ctx<<<gOut, 256>>>(SP, vsp, ctx);

    // final: out = ctx @ Wo^T + bo   [8192, 768]
    gemm_nt128<2><<<gProj, 256>>>(ctx, Wo, out, bo, EMB, EMB, 1.f, 0, 0, 0);
}

// round 9
// speedup vs baseline: 2.2029x; 2.2029x over previous
#include <cuda_runtime.h>
#include <cuda_bf16.h>
#include <cstdint>
#include <cstddef>

// Problem constants
#define NB 8
#define NH 12
#define SQ 1024
#define DH 64
#define EMB 768
#define BHC (NB*NH)      // 96

// ---------------- scratch (static device globals; no allocation) ----------------
__device__ float g_q  [NB*NH*SQ*DH];
__device__ float g_ksp[NB*NH*SQ*DH];
__device__ float g_kp [NB*NH*SQ*DH];
__device__ float g_vsp[NB*NH*SQ*DH];
__device__ float g_A1 [100663296];               // fp32 logits [bh][k][s]
__device__ float g_A2 [100663296];               // fp32 logits [bh][p][s]
__device__ __nv_bfloat16 g_A1h[100663296];       // bf16 softmaxed [bh][k][s]
__device__ __nv_bfloat16 g_A2h[100663296];       // bf16 softmaxed [bh][p][s]
__device__ float g_SP [100663296];               // [bh][p][k]
__device__ float g_ctx[NB*SQ*EMB];               // [b,p, h*64+d]

// =====================  helpers (baseline sm_90 ISA only — no 'a' features) =====
__device__ __forceinline__ uint32_t smem_to_u32(const void* p) {
    uint32_t a;
    asm("{ .reg .u64 t; cvta.to.shared.u64 t, %1; cvt.u32.u64 %0, t; }" : "=r"(a) : "l"(p));
    return a;
}
__device__ __forceinline__ void cp_async16(uint32_t saddr, const void* gaddr) {
    asm volatile("cp.async.cg.shared.global [%0], [%1], 16;\n" :: "r"(saddr), "l"(gaddr));
}
#define CP_COMMIT()  asm volatile("cp.async.commit_group;\n" ::: "memory")
#define CP_WAIT(n)   asm volatile("cp.async.wait_group %0;\n" :: "n"(n) : "memory")
#define SWZ128(o) ((o) ^ (((o) >> 3) & 0x70))

__device__ __forceinline__ void ldmatrix_x4(uint32_t* r, uint32_t addr) {
    asm volatile("ldmatrix.sync.aligned.m8n8.x4.shared.b16 {%0,%1,%2,%3}, [%4];"
        : "=r"(r[0]), "=r"(r[1]), "=r"(r[2]), "=r"(r[3]) : "r"(addr));
}
__device__ __forceinline__ void mma16816(float* c, const uint32_t* a, uint32_t b0, uint32_t b1) {
    asm volatile("mma.sync.aligned.m16n8k16.row.col.f32.bf16.bf16.f32 "
        "{%0,%1,%2,%3}, {%4,%5,%6,%7}, {%8,%9}, {%0,%1,%2,%3};"
        : "+f"(c[0]), "+f"(c[1]), "+f"(c[2]), "+f"(c[3])
        : "r"(a[0]), "r"(a[1]), "r"(a[2]), "r"(a[3]), "r"(b0), "r"(b1));
}

// =================================================================================
// sp2p tensor-core kernel: per bh, SP[p,k'] = sum_s A2h[p,s] * A1h[k',s]
// CTA tile 128(m) x 64(n), BK=64 (128B rows, SW128 swizzle), double-buffered cp.async.
// 8 warps, 4x2 layout, warp tile 32x32 via mma.sync m16n8k16 bf16.
// =================================================================================
__global__ void __launch_bounds__(256)
sp2p_mma(const __nv_bfloat16* __restrict__ A2h, const __nv_bfloat16* __restrict__ A1h,
         float* __restrict__ SP)
{
    __shared__ __align__(1024) char smem_buf[49152];   // 2 x (16KB A + 8KB B)
    const uint32_t sb = smem_to_u32(smem_buf);
    const int tid = threadIdx.x, wid = tid >> 5, lane = tid & 31;
    const int bh = blockIdx.z;

    const __nv_bfloat16* Arow = A2h + (size_t)bh * SQ * SQ + (size_t)blockIdx.y * 128 * SQ;
    const __nv_bfloat16* Brow = A1h + (size_t)bh * SQ * SQ + (size_t)blockIdx.x * 64  * SQ;

    auto load_chunk = [&](int kc, int q) {
        uint32_t bA = sb + (uint32_t)q * 24576u;
        uint32_t bB = bA + 16384u;
        #pragma unroll
        for (int i = 0; i < 4; i++) {                 // A: 128 rows x 8 chunks
            int u = tid + i * 256, r = u >> 3, c = u & 7;
            cp_async16(bA + SWZ128((uint32_t)(r * 128 + c * 16)),
                       Arow + (size_t)r * SQ + kc * 64 + c * 8);
        }
        #pragma unroll
        for (int i = 0; i < 2; i++) {                 // B: 64 rows x 8 chunks
            int u = tid + i * 256, r = u >> 3, c = u & 7;
            cp_async16(bB + SWZ128((uint32_t)(r * 128 + c * 16)),
                       Brow + (size_t)r * SQ + kc * 64 + c * 8);
        }
        CP_COMMIT();
    };

    load_chunk(0, 0);
    load_chunk(1, 1);

    const int wm = (wid & 3) * 32;    // warp m offset (0..96)
    const int wn = (wid >> 2) * 32;   // warp n offset (0 or 32)
    const int lg = lane >> 3;         // ldmatrix matrix index 0..3
    const int lr = lane & 7;          // row within matrix

    float acc[2][4][4];
    #pragma unroll
    for (int im = 0; im < 2; im++)
        #pragma unroll
        for (int in = 0; in < 4; in++)
            #pragma unroll
            for (int r = 0; r < 4; r++) acc[im][in][r] = 0.f;

    #pragma unroll 1
    for (int kc = 0; kc < 16; kc++) {
        if (kc == 15) { CP_WAIT(0); } else { CP_WAIT(1); }
        __syncthreads();
        uint32_t bA = sb + (uint32_t)(kc & 1) * 24576u;
        uint32_t bB = bA + 16384u;

        #pragma unroll
        for (int ks = 0; ks < 4; ks++) {
            const int kb = ks * 32 + (lg >> 1) * 16;       // byte offset in 128B row
            uint32_t a[2][4], b[2][4];
            #pragma unroll
            for (int im = 0; im < 2; im++) {
                int row = wm + im * 16 + (lg & 1) * 8 + lr;
                ldmatrix_x4(a[im], bA + SWZ128((uint32_t)(row * 128 + kb)));
            }
            #pragma unroll
            for (int ib = 0; ib < 2; ib++) {
                int row = wn + ib * 16 + (lg & 1) * 8 + lr;
                ldmatrix_x4(b[ib], bB + SWZ128((uint32_t)(row * 128 + kb)));
            }
            #pragma unroll
            for (int im = 0; im < 2; im++)
                #pragma unroll
                for (int in = 0; in < 4; in++) {
                    int ib = in >> 1, hi = in & 1;
                    mma16816(acc[im][in], a[im], b[ib][hi], b[ib][2 + hi]);
                }
        }
        __syncthreads();
        if (kc < 14) load_chunk(kc + 2, kc & 1);
    }

    // epilogue: d0,d1 at (m=t/4, n=(t%4)*2), d2,d3 at m+8
    float* C = SP + (size_t)bh * SQ * SQ + (size_t)(blockIdx.y * 128) * SQ + blockIdx.x * 64;
    #pragma unroll
    for (int im = 0; im < 2; im++)
        #pragma unroll
        for (int half = 0; half < 2; half++) {
            int m = wm + im * 16 + (lane >> 2) + half * 8;
            #pragma unroll
            for (int in = 0; in < 4; in++) {
                int n = wn + in * 8 + (lane & 3) * 2;
                *(float2*)(C + (size_t)m * SQ + n) =
                    make_float2(acc[im][in][half * 2], acc[im][in][half * 2 + 1]);
            }
        }
}

// =================================================================================
// NT GEMM, 128x128 tile, BK=8, 256 threads, 8x8 micro-tile (fp32).
// EPI 0: plain store; EPI 1: (acc+bias)*alpha -> head layout; EPI 2: (acc+bias)*alpha plain.
// =================================================================================
template<int EPI>
__global__ void __launch_bounds__(256)
gemm_nt128(const float* __restrict__ Ab, const float* __restrict__ Bb,
           float* __restrict__ Cb, const float* __restrict__ bias,
           int K, int ldc, float alpha,
           size_t sA, size_t sB, size_t sC)
{
    const int m0 = blockIdx.y * 128;
    const int n0 = blockIdx.x * 128;
    const float* A  = Ab + (size_t)blockIdx.z * sA + (size_t)m0 * K;
    const float* Bp = Bb + (size_t)blockIdx.z * sB + (size_t)n0 * K;
    float* C = Cb + (size_t)blockIdx.z * sC;

    __shared__ float As[8][128];
    __shared__ float Bs[8][128];

    const int tid = threadIdx.x;
    const int lr = tid >> 1;
    const int lc = (tid & 1) * 4;
    const int tx = tid & 15;
    const int ty = tid >> 4;

    float acc[8][8];
    #pragma unroll
    for (int i = 0; i < 8; i++)
        #pragma unroll
        for (int j = 0; j < 8; j++) acc[i][j] = 0.f;

    for (int k0 = 0; k0 < K; k0 += 8) {
        float4 av = *(const float4*)(A  + (size_t)lr * K + k0 + lc);
        float4 bv = *(const float4*)(Bp + (size_t)lr * K + k0 + lc);
        __syncthreads();
        As[lc+0][lr] = av.x; As[lc+1][lr] = av.y; As[lc+2][lr] = av.z; As[lc+3][lr] = av.w;
        Bs[lc+0][lr] = bv.x; Bs[lc+1][lr] = bv.y; Bs[lc+2][lr] = bv.z; Bs[lc+3][lr] = bv.w;
        __syncthreads();

        #pragma unroll
        for (int kk = 0; kk < 8; kk++) {
            float a[8], b[8];
            *(float4*)&a[0] = *(const float4*)&As[kk][ty*4];
            *(float4*)&a[4] = *(const float4*)&As[kk][64 + ty*4];
            *(float4*)&b[0] = *(const float4*)&Bs[kk][tx*4];
            *(float4*)&b[4] = *(const float4*)&Bs[kk][64 + tx*4];
            #pragma unroll
            for (int i = 0; i < 8; i++)
                #pragma unroll
                for (int j = 0; j < 8; j++)
                    acc[i][j] += a[i] * b[j];
        }
    }

    #pragma unroll
    for (int i = 0; i < 8; i++) {
        int m = m0 + ((i < 4) ? (ty*4 + i) : (64 + ty*4 + i - 4));
        #pragma unroll
        for (int j = 0; j < 8; j++) {
            int n = n0 + ((j < 4) ? (tx*4 + j) : (64 + tx*4 + j - 4));
            if (EPI == 0) {
                C[(size_t)m * ldc + n] = acc[i][j];
            } else {
                float v = (acc[i][j] + bias[n]) * alpha;
                if (EPI == 1) {
                    int bb = m >> 10, s = m & 1023;
                    int h  = n >> 6,  d = n & 63;
                    C[((((size_t)bb * NH + h) * SQ) + s) * DH + d] = v;
                } else {
                    C[(size_t)m * ldc + n] = v;
                }
            }
        }
    }
}

// =================================================================================
// NN GEMM: per (b,h): ctx = SP[1024,1024] @ V[1024,64] -> ctx[b,p,h*64+d] (fp32)
// =================================================================================
__global__ void __launch_bounds__(256)
gemm_nn_ctx(const float* __restrict__ Sp, const float* __restrict__ V, float* __restrict__ ctx)
{
    const int bh = blockIdx.z;
    const int b = bh / NH, h = bh % NH;
    const int m0 = blockIdx.y * 64;
    const float* A  = Sp + (size_t)bh * SQ * SQ + (size_t)m0 * SQ;
    const float* Bv = V  + (size_t)bh * SQ * DH;

    __shared__ float As[16][64];
    __shared__ float Bs[16][64];

    const int tid = threadIdx.x;
    const int alr = tid >> 2, alc = (tid & 3) * 4;
    const int bkr = tid >> 4, bnc = (tid & 15) * 4;
    const int tx = tid & 15, ty = tid >> 4;

    float acc[4][4];
    #pragma unroll
    for (int i = 0; i < 4; i++)
        #pragma unroll
        for (int j = 0; j < 4; j++) acc[i][j] = 0.f;

    for (int k0 = 0; k0 < SQ; k0 += 16) {
        float4 av = *(const float4*)(A  + (size_t)alr * SQ + k0 + alc);
        float4 bv = *(const float4*)(Bv + (size_t)(k0 + bkr) * DH + bnc);
        __syncthreads();
        As[alc+0][alr] = av.x; As[alc+1][alr] = av.y; As[alc+2][alr] = av.z; As[alc+3][alr] = av.w;
        *(float4*)&Bs[bkr][bnc] = bv;
        __syncthreads();

        #pragma unroll
        for (int kk = 0; kk < 16; kk++) {
            float4 a = *(const float4*)&As[kk][ty*4];
            float4 bq4 = *(const float4*)&Bs[kk][tx*4];
            acc[0][0] += a.x*bq4.x; acc[0][1] += a.x*bq4.y; acc[0][2] += a.x*bq4.z; acc[0][3] += a.x*bq4.w;
            acc[1][0] += a.y*bq4.x; acc[1][1] += a.y*bq4.y; acc[1][2] += a.y*bq4.z; acc[1][3] += a.y*bq4.w;
            acc[2][0] += a.z*bq4.x; acc[2][1] += a.z*bq4.y; acc[2][2] += a.z*bq4.z; acc[2][3] += a.z*bq4.w;
            acc[3][0] += a.w*bq4.x; acc[3][1] += a.w*bq4.y; acc[3][2] += a.w*bq4.z; acc[3][3] += a.w*bq4.w;
        }
    }

    #pragma unroll
    for (int i = 0; i < 4; i++) {
        int pIdx = m0 + ty * 4 + i;
        float* dst = ctx + ((size_t)(b * SQ + pIdx)) * EMB + h * DH + tx * 4;
        dst[0] = acc[i][0]; dst[1] = acc[i][1]; dst[2] = acc[i][2]; dst[3] = acc[i][3];
    }
}

// =================================================================================
// Row softmax over rows of length 1024: fp32 in-place and fp32->bf16 variants.
// =================================================================================
__device__ __forceinline__ float4 softmax_core(float4 v, int t, float* red) {
    float m = fmaxf(fmaxf(v.x, v.y), fmaxf(v.z, v.w));
    #pragma unroll
    for (int o = 16; o; o >>= 1) m = fmaxf(m, __shfl_xor_sync(0xffffffffu, m, o));
    if ((t & 31) == 0) red[t >> 5] = m;
    __syncthreads();
    m = red[0];
    #pragma unroll
    for (int i = 1; i < 8; i++) m = fmaxf(m, red[i]);

    v.x = __expf(v.x - m); v.y = __expf(v.y - m);
    v.z = __expf(v.z - m); v.w = __expf(v.w - m);
    float s = v.x + v.y + v.z + v.w;
    #pragma unroll
    for (int o = 16; o; o >>= 1) s += __shfl_xor_sync(0xffffffffu, s, o);
    __syncthreads();
    if ((t & 31) == 0) red[t >> 5] = s;
    __syncthreads();
    s = red[0];
    #pragma unroll
    for (int i = 1; i < 8; i++) s += red[i];

    float inv = 1.0f / s;
    v.x *= inv; v.y *= inv; v.z *= inv; v.w *= inv;
    return v;
}

__global__ void __launch_bounds__(256)
softmax_rows(float* __restrict__ data)
{
    float* rowp = data + (size_t)blockIdx.x * 1024;
    const int t = threadIdx.x;
    __shared__ float red[8];
    float4 v = ((float4*)rowp)[t];
    v = softmax_core(v, t, red);
    ((float4*)rowp)[t] = v;
}

__global__ void __launch_bounds__(256)
softmax_rows_bf16(const float* __restrict__ in, __nv_bfloat16* __restrict__ out)
{
    const float* rowp = in + (size_t)blockIdx.x * 1024;
    __nv_bfloat16* orow = out + (size_t)blockIdx.x * 1024;
    const int t = threadIdx.x;
    __shared__ float red[8];
    float4 v = ((float4*)rowp)[t];
    v = softmax_core(v, t, red);
    __nv_bfloat162 p0, p1;
    p0.x = __float2bfloat16(v.x); p0.y = __float2bfloat16(v.y);
    p1.x = __float2bfloat16(v.z); p1.y = __float2bfloat16(v.w);
    ((__nv_bfloat162*)orow)[2*t]   = p0;
    ((__nv_bfloat162*)orow)[2*t+1] = p1;
}

// =================================================================================
extern "C" void kernel_launch(void* const* d_in, const int* in_sizes, int n_in,
                              void* d_out, int out_size)
{
    const float* l    = (const float*)d_in[0];
    const float* sp   = (const float*)d_in[1];
    const float* pp   = (const float*)d_in[2];
    const float* Wq   = (const float*)d_in[3];
    const float* bq   = (const float*)d_in[4];
    const float* Wksp = (const float*)d_in[5];
    const float* bksp = (const float*)d_in[6];
    const float* Wkp  = (const float*)d_in[7];
    const float* bkp  = (const float*)d_in[8];
    const float* Wvsp = (const float*)d_in[9];
    const float* bvsp = (const float*)d_in[10];
    const float* Wo   = (const float*)d_in[13];
    const float* bo   = (const float*)d_in[14];
    float* out = (float*)d_out;

    float *q, *ksp, *kp, *vsp, *A1, *A2, *SP, *ctx;
    __nv_bfloat16 *A1h, *A2h;
    cudaGetSymbolAddress((void**)&q,   g_q);
    cudaGetSymbolAddress((void**)&ksp, g_ksp);
    cudaGetSymbolAddress((void**)&kp,  g_kp);
    cudaGetSymbolAddress((void**)&vsp, g_vsp);
    cudaGetSymbolAddress((void**)&A1,  g_A1);
    cudaGetSymbolAddress((void**)&A2,  g_A2);
    cudaGetSymbolAddress((void**)&A1h, g_A1h);
    cudaGetSymbolAddress((void**)&A2h, g_A2h);
    cudaGetSymbolAddress((void**)&SP,  g_SP);
    cudaGetSymbolAddress((void**)&ctx, g_ctx);

    const float scale = 0.125f;
    const size_t sHead = (size_t)SQ * DH;
    const size_t sMat  = (size_t)SQ * SQ;

    dim3 gProj(EMB / 128, (NB * SQ) / 128, 1);

    gemm_nt128<1><<<gProj, 256>>>(l,  Wq,   q,   bq,   EMB, 0, scale, 0, 0, 0);
    gemm_nt128<1><<<gProj, 256>>>(sp, Wksp, ksp, bksp, EMB, 0, scale, 0, 0, 0);
    gemm_nt128<1><<<gProj, 256>>>(pp, Wkp,  kp,  bkp,  EMB, 0, scale, 0, 0, 0);
    gemm_nt128<1><<<gProj, 256>>>(sp, Wvsp, vsp, bvsp, EMB, 0, scale, 0, 0, 0);

    dim3 gLog(SQ / 128, SQ / 128, BHC);
    gemm_nt128<0><<<gLog, 256>>>(ksp, q, A1, nullptr, DH, SQ, 1.f, sHead, sHead, sMat);
    gemm_nt128<0><<<gLog, 256>>>(kp,  q, A2, nullptr, DH, SQ, 1.f, sHead, sHead, sMat);

    // softmax over s (row-wise), emitting bf16 for the tensor-core GEMM
    softmax_rows_bf16<<<BHC * SQ, 256>>>(A1, A1h);
    softmax_rows_bf16<<<BHC * SQ, 256>>>(A2, A2h);

    // sp2p[p,k] = sum_s A2[p,s] * A1[k,s]  via mma.sync bf16 (fp32 accumulate)
    dim3 gSp(SQ / 64, SQ / 128, BHC);            // (16, 8, 96)
    sp2p_mma<<<gSp, 256>>>(A2h, A1h, SP);

    // softmax over k (row-wise, fp32)
    softmax_rows<<<BHC * SQ, 256>>>(SP);

    // ctx[b,p,h*64+d] = sum_k SP[p,k] * vsp[k,d]   (fp32)
    dim3 gOut(1, SQ / 64, BHC);
    gemm_nn_ctx<<<gOut, 256>>>(SP, vsp, ctx);

    // final: out = ctx @ Wo^T + bo
    gemm_nt128<2><<<gProj, 256>>>(ctx, Wo, out, bo, EMB, EMB, 1.f, 0, 0, 0);
}

// round 10
// speedup vs baseline: 3.7352x; 1.6956x over previous
#include <cuda_runtime.h>
#include <cuda_bf16.h>
#include <cstdint>
#include <cstddef>

// Problem constants
#define NB 8
#define NH 12
#define SQ 1024
#define DH 64
#define EMB 768
#define BHC (NB*NH)      // 96
#define ACT_N (NB*SQ*EMB)   // 6291456 elements (activations / head tensors)
#define WN (EMB*EMB)        // 589824 per weight

// ---------------- scratch (static device globals; no allocation) ----------------
// bf16 hi/lo splits of inputs
__device__ __nv_bfloat16 g_lh [ACT_N], g_ll [ACT_N];
__device__ __nv_bfloat16 g_sph[ACT_N], g_spl[ACT_N];
__device__ __nv_bfloat16 g_pph[ACT_N], g_ppl[ACT_N];
__device__ __nv_bfloat16 g_Wh [5*WN],  g_Wl [5*WN];     // Wq,Wksp,Wkp,Wvsp,Wo
// projected tensors (head layout [b,h,s,d]) hi/lo
__device__ __nv_bfloat16 g_qh  [ACT_N], g_ql  [ACT_N];
__device__ __nv_bfloat16 g_ksph[ACT_N], g_kspl[ACT_N];
__device__ __nv_bfloat16 g_kph [ACT_N], g_kpl [ACT_N];
__device__ __nv_bfloat16 g_vTh [ACT_N], g_vTl [ACT_N];  // transposed head layout [b,h,d,s]
// logits + softmaxed
__device__ float g_A1 [100663296];                // [bh][k][s]
__device__ float g_A2 [100663296];                // [bh][p][s]
__device__ __nv_bfloat16 g_A1h[100663296], g_A2h[100663296];
__device__ float g_SP [100663296];                // [bh][p][k]
__device__ __nv_bfloat16 g_SPh[100663296], g_SPl[100663296];
__device__ __nv_bfloat16 g_ctxh[ACT_N], g_ctxl[ACT_N];  // [b,p,e] hi/lo

// =====================  helpers (baseline ISA only — no 'a' features) =====
__device__ __forceinline__ uint32_t smem_to_u32(const void* p) {
    uint32_t a;
    asm("{ .reg .u64 t; cvta.to.shared.u64 t, %1; cvt.u32.u64 %0, t; }" : "=r"(a) : "l"(p));
    return a;
}
__device__ __forceinline__ void cp_async16(uint32_t saddr, const void* gaddr) {
    asm volatile("cp.async.cg.shared.global [%0], [%1], 16;\n" :: "r"(saddr), "l"(gaddr));
}
#define CP_COMMIT()  asm volatile("cp.async.commit_group;\n" ::: "memory")
#define CP_WAIT(n)   asm volatile("cp.async.wait_group %0;\n" :: "n"(n) : "memory")
#define SWZ128(o) ((o) ^ (((o) >> 3) & 0x70))

__device__ __forceinline__ void ldmatrix_x4(uint32_t* r, uint32_t addr) {
    asm volatile("ldmatrix.sync.aligned.m8n8.x4.shared.b16 {%0,%1,%2,%3}, [%4];"
        : "=r"(r[0]), "=r"(r[1]), "=r"(r[2]), "=r"(r[3]) : "r"(addr));
}
__device__ __forceinline__ void mma16816(float* c, const uint32_t* a, uint32_t b0, uint32_t b1) {
    asm volatile("mma.sync.aligned.m16n8k16.row.col.f32.bf16.bf16.f32 "
        "{%0,%1,%2,%3}, {%4,%5,%6,%7}, {%8,%9}, {%0,%1,%2,%3};"
        : "+f"(c[0]), "+f"(c[1]), "+f"(c[2]), "+f"(c[3])
        : "r"(a[0]), "r"(a[1]), "r"(a[2]), "r"(a[3]), "r"(b0), "r"(b1));
}
__device__ __forceinline__ void split1(float v, __nv_bfloat16& h, __nv_bfloat16& l) {
    h = __float2bfloat16(v);
    l = __float2bfloat16(v - __bfloat162float(h));
}

// =================================================================================
// Unified bf16 NT GEMM: C[m,n] = sum over segments of sum_k Aseg[m,k]*Bseg[n,k].
// CTA tile 128(m) x 64(n), BK=64 (128B rows, SW128), double-buffered cp.async.
// 8 warps (4x2), warp tile 32x32, mma.sync m16n8k16 bf16 -> fp32 acc.
// Segment list (up to 3) implements the fp32-via-bf16 split:
//   (A_hi,B_hi), (A_lo,B_hi), (A_hi,B_lo)  -> exact product minus lo*lo (~2^-18).
// Epilogues:
//  0: fp32 store  Cf[z*sC + m*ldc + n]
//  1: (acc+bias[e])*alpha -> hi/lo bf16 at head layout [b,h,s,d]   (m=b*1024+s, e=n0+n)
//  2: same but transposed head layout [b,h,d,s]                    (vsp^T)
//  3: acc -> hi/lo bf16 at ctx layout [b, p, h*64+d]               (z=bh, m=p, n=d)
//  4: acc+bias[n] -> fp32 out[m*EMB + n]                           (final)
// =================================================================================
template<int EPI>
__global__ void __launch_bounds__(256)
gemm_bf16nt(const __nv_bfloat16* __restrict__ A0, const __nv_bfloat16* __restrict__ A1p,
            const __nv_bfloat16* __restrict__ A2p,
            const __nv_bfloat16* __restrict__ B0, const __nv_bfloat16* __restrict__ B1p,
            const __nv_bfloat16* __restrict__ B2p,
            int nseg, int K, size_t sA, size_t sB,
            float* __restrict__ Cf, __nv_bfloat16* __restrict__ Chi,
            __nv_bfloat16* __restrict__ Clo,
            const float* __restrict__ bias, float alpha, int ldc, size_t sC)
{
    __shared__ __align__(1024) char smem_buf[49152];   // 2 x (16KB A + 8KB B)
    const uint32_t sb = smem_to_u32(smem_buf);
    const int tid = threadIdx.x, wid = tid >> 5, lane = tid & 31;
    const int z = blockIdx.z;
    const int m0 = blockIdx.y * 128, n0 = blockIdx.x * 64;
    const int cps = K >> 6;                  // 64-elem chunks per segment

    int l_seg = 0, l_kc = 0;                 // loader cursor (advances once per call)
    auto load_chunk = [&](int buf) {
        const __nv_bfloat16* Ab = (l_seg == 0) ? A0 : ((l_seg == 1) ? A1p : A2p);
        const __nv_bfloat16* Bb = (l_seg == 0) ? B0 : ((l_seg == 1) ? B1p : B2p);
        Ab += (size_t)z * sA + (size_t)m0 * K + l_kc * 64;
        Bb += (size_t)z * sB + (size_t)n0 * K + l_kc * 64;
        uint32_t bA = sb + (uint32_t)buf * 24576u;
        uint32_t bB = bA + 16384u;
        #pragma unroll
        for (int i = 0; i < 4; i++) {                 // A: 128 rows x 8 x 16B
            int u = tid + i * 256, r = u >> 3, c = u & 7;
            cp_async16(bA + SWZ128((uint32_t)(r * 128 + c * 16)), Ab + (size_t)r * K + c * 8);
        }
        #pragma unroll
        for (int i = 0; i < 2; i++) {                 // B: 64 rows x 8 x 16B
            int u = tid + i * 256, r = u >> 3, c = u & 7;
            cp_async16(bB + SWZ128((uint32_t)(r * 128 + c * 16)), Bb + (size_t)r * K + c * 8);
        }
        CP_COMMIT();
        if (++l_kc == cps) { l_kc = 0; ++l_seg; }
    };

    const int T = nseg * cps;
    load_chunk(0);
    load_chunk(1);

    const int wm = (wid & 3) * 32;    // warp m offset
    const int wn = (wid >> 2) * 32;   // warp n offset
    const int lg = lane >> 3;
    const int lr = lane & 7;

    float acc[2][4][4];
    #pragma unroll
    for (int im = 0; im < 2; im++)
        #pragma unroll
        for (int in = 0; in < 4; in++)
            #pragma unroll
            for (int r = 0; r < 4; r++) acc[im][in][r] = 0.f;

    #pragma unroll 1
    for (int t = 0; t < T; t++) {
        if (t == T - 1) { CP_WAIT(0); } else { CP_WAIT(1); }
        __syncthreads();
        uint32_t bA = sb + (uint32_t)(t & 1) * 24576u;
        uint32_t bB = bA + 16384u;

        #pragma unroll
        for (int ks = 0; ks < 4; ks++) {
            const int kb = ks * 32 + (lg >> 1) * 16;
            uint32_t a[2][4], b[2][4];
            #pragma unroll
            for (int im = 0; im < 2; im++) {
                int row = wm + im * 16 + (lg & 1) * 8 + lr;
                ldmatrix_x4(a[im], bA + SWZ128((uint32_t)(row * 128 + kb)));
            }
            #pragma unroll
            for (int ib = 0; ib < 2; ib++) {
                int row = wn + ib * 16 + (lg & 1) * 8 + lr;
                ldmatrix_x4(b[ib], bB + SWZ128((uint32_t)(row * 128 + kb)));
            }
            #pragma unroll
            for (int im = 0; im < 2; im++)
                #pragma unroll
                for (int in = 0; in < 4; in++) {
                    int ib = in >> 1, hi = in & 1;
                    mma16816(acc[im][in], a[im], b[ib][hi], b[ib][2 + hi]);
                }
        }
        __syncthreads();
        if (t + 2 < T) load_chunk(t & 1);
    }

    // ---------------- epilogue ----------------
    #pragma unroll
    for (int im = 0; im < 2; im++)
        #pragma unroll
        for (int half = 0; half < 2; half++) {
            int m = wm + im * 16 + (lane >> 2) + half * 8;   // local m (0..127)
            #pragma unroll
            for (int in = 0; in < 4; in++) {
                int n = wn + in * 8 + (lane & 3) * 2;        // local n (0..62, even)
                float v0 = acc[im][in][half * 2 + 0];
                float v1 = acc[im][in][half * 2 + 1];

                if (EPI == 0) {
                    *(float2*)(Cf + (size_t)z * sC + (size_t)(m0 + m) * ldc + n0 + n) =
                        make_float2(v0, v1);
                } else if (EPI == 1 || EPI == 2) {
                    int e = n0 + n, mg = m0 + m;
                    v0 = (v0 + bias[e]) * alpha;
                    v1 = (v1 + bias[e + 1]) * alpha;
                    int b = mg >> 10, s = mg & 1023, h = e >> 6, d = e & 63;
                    __nv_bfloat16 h0, l0, h1, l1;
                    split1(v0, h0, l0); split1(v1, h1, l1);
                    if (EPI == 1) {
                        size_t idx = (((size_t)(b * NH + h)) * SQ + s) * DH + d;
                        __nv_bfloat162 hp; hp.x = h0; hp.y = h1;
                        __nv_bfloat162 lp; lp.x = l0; lp.y = l1;
                        *(__nv_bfloat162*)(Chi + idx) = hp;
                        *(__nv_bfloat162*)(Clo + idx) = lp;
                    } else {
                        size_t base = (((size_t)(b * NH + h)) * DH + d) * SQ + s;
                        Chi[base] = h0;      Clo[base] = l0;
                        Chi[base + SQ] = h1; Clo[base + SQ] = l1;
                    }
                } else if (EPI == 3) {
                    int b = z / NH, h = z - b * NH;
                    int p = m0 + m;
                    size_t idx = ((size_t)(b * SQ + p)) * EMB + h * DH + (n0 + n);
                    __nv_bfloat16 h0, l0, h1, l1;
                    split1(v0, h0, l0); split1(v1, h1, l1);
                    __nv_bfloat162 hp; hp.x = h0; hp.y = h1;
                    __nv_bfloat162 lp; lp.x = l0; lp.y = l1;
                    *(__nv_bfloat162*)(Chi + idx) = hp;
                    *(__nv_bfloat162*)(Clo + idx) = lp;
                } else {  // EPI == 4
                    int e = n0 + n;
                    *(float2*)(Cf + (size_t)(m0 + m) * EMB + e) =
                        make_float2(v0 + bias[e], v1 + bias[e + 1]);
                }
            }
        }
}

// =================================================================================
// fp32 -> (hi, lo) bf16 split, elementwise (n multiple of 4)
// =================================================================================
__global__ void __launch_bounds__(256)
split_pair(const float* __restrict__ x, __nv_bfloat16* __restrict__ hi,
           __nv_bfloat16* __restrict__ lo, int n)
{
    int i = blockIdx.x * 256 + threadIdx.x;
    if (i * 4 >= n) return;
    float4 v = ((const float4*)x)[i];
    __nv_bfloat16 h0, l0, h1, l1, h2, l2, h3, l3;
    split1(v.x, h0, l0); split1(v.y, h1, l1);
    split1(v.z, h2, l2); split1(v.w, h3, l3);
    __nv_bfloat162 ha, hb, la, lb;
    ha.x = h0; ha.y = h1; hb.x = h2; hb.y = h3;
    la.x = l0; la.y = l1; lb.x = l2; lb.y = l3;
    ((__nv_bfloat162*)hi)[2 * i]     = ha;
    ((__nv_bfloat162*)hi)[2 * i + 1] = hb;
    ((__nv_bfloat162*)lo)[2 * i]     = la;
    ((__nv_bfloat162*)lo)[2 * i + 1] = lb;
}

// =================================================================================
// Row softmax over rows of length 1024 (contiguous).
// =================================================================================
__device__ __forceinline__ float4 softmax_core(float4 v, int t, float* red) {
    float m = fmaxf(fmaxf(v.x, v.y), fmaxf(v.z, v.w));
    #pragma unroll
    for (int o = 16; o; o >>= 1) m = fmaxf(m, __shfl_xor_sync(0xffffffffu, m, o));
    if ((t & 31) == 0) red[t >> 5] = m;
    __syncthreads();
    m = red[0];
    #pragma unroll
    for (int i = 1; i < 8; i++) m = fmaxf(m, red[i]);

    v.x = __expf(v.x - m); v.y = __expf(v.y - m);
    v.z = __expf(v.z - m); v.w = __expf(v.w - m);
    float s = v.x + v.y + v.z + v.w;
    #pragma unroll
    for (int o = 16; o; o >>= 1) s += __shfl_xor_sync(0xffffffffu, s, o);
    __syncthreads();
    if ((t & 31) == 0) red[t >> 5] = s;
    __syncthreads();
    s = red[0];
    #pragma unroll
    for (int i = 1; i < 8; i++) s += red[i];

    float inv = 1.0f / s;
    v.x *= inv; v.y *= inv; v.z *= inv; v.w *= inv;
    return v;
}

__global__ void __launch_bounds__(256)
softmax_rows_bf16(const float* __restrict__ in, __nv_bfloat16* __restrict__ out)
{
    const float* rowp = in + (size_t)blockIdx.x * 1024;
    __nv_bfloat16* orow = out + (size_t)blockIdx.x * 1024;
    const int t = threadIdx.x;
    __shared__ float red[8];
    float4 v = ((float4*)rowp)[t];
    v = softmax_core(v, t, red);
    __nv_bfloat162 p0, p1;
    p0.x = __float2bfloat16(v.x); p0.y = __float2bfloat16(v.y);
    p1.x = __float2bfloat16(v.z); p1.y = __float2bfloat16(v.w);
    ((__nv_bfloat162*)orow)[2 * t]     = p0;
    ((__nv_bfloat162*)orow)[2 * t + 1] = p1;
}

__global__ void __launch_bounds__(256)
softmax_rows_split(const float* __restrict__ in, __nv_bfloat16* __restrict__ hi,
                   __nv_bfloat16* __restrict__ lo)
{
    const float* rowp = in + (size_t)blockIdx.x * 1024;
    __nv_bfloat16* hrow = hi + (size_t)blockIdx.x * 1024;
    __nv_bfloat16* lrow = lo + (size_t)blockIdx.x * 1024;
    const int t = threadIdx.x;
    __shared__ float red[8];
    float4 v = ((float4*)rowp)[t];
    v = softmax_core(v, t, red);
    __nv_bfloat16 h0, l0, h1, l1, h2, l2, h3, l3;
    split1(v.x, h0, l0); split1(v.y, h1, l1);
    split1(v.z, h2, l2); split1(v.w, h3, l3);
    __nv_bfloat162 ha, hb, la, lb;
    ha.x = h0; ha.y = h1; hb.x = h2; hb.y = h3;
    la.x = l0; la.y = l1; lb.x = l2; lb.y = l3;
    ((__nv_bfloat162*)hrow)[2 * t]     = ha;
    ((__nv_bfloat162*)hrow)[2 * t + 1] = hb;
    ((__nv_bfloat162*)lrow)[2 * t]     = la;
    ((__nv_bfloat162*)lrow)[2 * t + 1] = lb;
}

// =================================================================================
extern "C" void kernel_launch(void* const* d_in, const int* in_sizes, int n_in,
                              void* d_out, int out_size)
{
    const float* l    = (const float*)d_in[0];
    const float* sp   = (const float*)d_in[1];
    const float* pp   = (const float*)d_in[2];
    const float* Wq   = (const float*)d_in[3];
    const float* bq   = (const float*)d_in[4];
    const float* Wksp = (const float*)d_in[5];
    const float* bksp = (const float*)d_in[6];
    const float* Wkp  = (const float*)d_in[7];
    const float* bkp  = (const float*)d_in[8];
    const float* Wvsp = (const float*)d_in[9];
    const float* bvsp = (const float*)d_in[10];
    const float* Wo   = (const float*)d_in[13];
    const float* bo   = (const float*)d_in[14];
    float* out = (float*)d_out;

    __nv_bfloat16 *lh, *ll, *sph, *spl, *pph, *ppl, *Wh, *Wl;
    __nv_bfloat16 *qh, *ql, *ksph, *kspl, *kph, *kpl, *vTh, *vTl;
    __nv_bfloat16 *A1h, *A2h, *SPh, *SPl, *ctxh, *ctxl;
    float *A1, *A2, *SP;
    cudaGetSymbolAddress((void**)&lh,  g_lh);   cudaGetSymbolAddress((void**)&ll,  g_ll);
    cudaGetSymbolAddress((void**)&sph, g_sph);  cudaGetSymbolAddress((void**)&spl, g_spl);
    cudaGetSymbolAddress((void**)&pph, g_pph);  cudaGetSymbolAddress((void**)&ppl, g_ppl);
    cudaGetSymbolAddress((void**)&Wh,  g_Wh);   cudaGetSymbolAddress((void**)&Wl,  g_Wl);
    cudaGetSymbolAddress((void**)&qh,  g_qh);   cudaGetSymbolAddress((void**)&ql,  g_ql);
    cudaGetSymbolAddress((void**)&ksph, g_ksph); cudaGetSymbolAddress((void**)&kspl, g_kspl);
    cudaGetSymbolAddress((void**)&kph, g_kph);  cudaGetSymbolAddress((void**)&kpl, g_kpl);
    cudaGetSymbolAddress((void**)&vTh, g_vTh);  cudaGetSymbolAddress((void**)&vTl, g_vTl);
    cudaGetSymbolAddress((void**)&A1,  g_A1);   cudaGetSymbolAddress((void**)&A2,  g_A2);
    cudaGetSymbolAddress((void**)&A1h, g_A1h);  cudaGetSymbolAddress((void**)&A2h, g_A2h);
    cudaGetSymbolAddress((void**)&SP,  g_SP);
    cudaGetSymbolAddress((void**)&SPh, g_SPh);  cudaGetSymbolAddress((void**)&SPl, g_SPl);
    cudaGetSymbolAddress((void**)&ctxh, g_ctxh); cudaGetSymbolAddress((void**)&ctxl, g_ctxl);

    const float scale = 0.125f;  // 64^-0.5
    const size_t sHead = (size_t)SQ * DH;    // 65536
    const size_t sMat  = (size_t)SQ * SQ;    // 1048576

    // ---- split inputs to (hi, lo) bf16 ----
    split_pair<<<ACT_N / 1024, 256>>>(l,  lh,  ll,  ACT_N);
    split_pair<<<ACT_N / 1024, 256>>>(sp, sph, spl, ACT_N);
    split_pair<<<ACT_N / 1024, 256>>>(pp, pph, ppl, ACT_N);
    split_pair<<<WN / 1024, 256>>>(Wq,   Wh + 0 * WN, Wl + 0 * WN, WN);
    split_pair<<<WN / 1024, 256>>>(Wksp, Wh + 1 * WN, Wl + 1 * WN, WN);
    split_pair<<<WN / 1024, 256>>>(Wkp,  Wh + 2 * WN, Wl + 2 * WN, WN);
    split_pair<<<WN / 1024, 256>>>(Wvsp, Wh + 3 * WN, Wl + 3 * WN, WN);
    split_pair<<<WN / 1024, 256>>>(Wo,   Wh + 4 * WN, Wl + 4 * WN, WN);

    // ---- projections (split bf16, 3 segments), epilogue scales + head layout ----
    dim3 gProj(EMB / 64, (NB * SQ) / 128, 1);   // (12, 64)
    gemm_bf16nt<1><<<gProj, 256>>>(lh,  ll,  lh,  Wh + 0*WN, Wh + 0*WN, Wl + 0*WN,
                                   3, EMB, 0, 0, nullptr, qh,  ql,  bq,   scale, 0, 0);
    gemm_bf16nt<1><<<gProj, 256>>>(sph, spl, sph, Wh + 1*WN, Wh + 1*WN, Wl + 1*WN,
                                   3, EMB, 0, 0, nullptr, ksph, kspl, bksp, scale, 0, 0);
    gemm_bf16nt<1><<<gProj, 256>>>(pph, ppl, pph, Wh + 2*WN, Wh + 2*WN, Wl + 2*WN,
                                   3, EMB, 0, 0, nullptr, kph, kpl, bkp,  scale, 0, 0);
    gemm_bf16nt<2><<<gProj, 256>>>(sph, spl, sph, Wh + 3*WN, Wh + 3*WN, Wl + 3*WN,
                                   3, EMB, 0, 0, nullptr, vTh, vTl, bvsp, scale, 0, 0);

    // ---- transposed logits: A1[k,s] = ksp_k . q_s ; A2[p,s] = kp_p . q_s ----
    dim3 gLog(SQ / 64, SQ / 128, BHC);          // (16, 8, 96)
    gemm_bf16nt<0><<<gLog, 256>>>(ksph, kspl, ksph, qh, qh, ql,
                                  3, DH, sHead, sHead, A1, nullptr, nullptr, nullptr, 1.f, SQ, sMat);
    gemm_bf16nt<0><<<gLog, 256>>>(kph, kpl, kph, qh, qh, ql,
                                  3, DH, sHead, sHead, A2, nullptr, nullptr, nullptr, 1.f, SQ, sMat);

    // ---- softmax over s (row-wise) -> bf16 (single term; error averages out) ----
    softmax_rows_bf16<<<BHC * SQ, 256>>>(A1, A1h);
    softmax_rows_bf16<<<BHC * SQ, 256>>>(A2, A2h);

    // ---- sp2p[p,k] = sum_s A2[p,s] * A1[k,s]  (single-segment bf16) ----
    gemm_bf16nt<0><<<gLog, 256>>>(A2h, A2h, A2h, A1h, A1h, A1h,
                                  1, SQ, sMat, sMat, SP, nullptr, nullptr, nullptr, 1.f, SQ, sMat);

    // ---- softmax over k (row-wise) -> hi/lo split ----
    softmax_rows_split<<<BHC * SQ, 256>>>(SP, SPh, SPl);

    // ---- ctx[b,p,h*64+d] = sum_k SP[p,k] * vsp[k,d]  (split bf16 NT) ----
    dim3 gCtx(1, SQ / 128, BHC);                // (1, 8, 96)
    gemm_bf16nt<3><<<gCtx, 256>>>(SPh, SPl, SPh, vTh, vTh, vTl,
                                  3, SQ, sMat, sHead, nullptr, ctxh, ctxl, nullptr, 1.f, 0, 0);

    // ---- final: out = ctx @ Wo^T + bo ----
    gemm_bf16nt<4><<<gProj, 256>>>(ctxh, ctxl, ctxh, Wh + 4*WN, Wh + 4*WN, Wl + 4*WN,
                                   3, EMB, 0, 0, out, nullptr, nullptr, bo, 1.f, 0, 0);
}